// round 1
// baseline (speedup 1.0000x reference)
#include <cuda_runtime.h>
#include <cstdint>

#define Ndim 16
#define Cdim 128
#define Sdim 16384
#define Kdim 64
#define TILE_S 128
#define THREADS 256
#define TILES_PER_BLOCK 8
#define BLOCKS_PER_N 16   // 16 blocks * 8 tiles * 128 s = 16384 = Sdim
#define GRID (Ndim * BLOCKS_PER_N)

#define XS_PAD 132   // xs[c][s], stride 132: GEMM1 b-loads contiguous, conflict-free
#define XT_PAD 134   // xt[s][c], stride 134: write bank stride 6 -> 2-way worst case
#define LG_PAD 132

// Shared layout (floats):
// fw   : 64*128            = 8192
// bias : 64
// xs   : 128*132           = 16896
// xt   : 128*134           = 17152
// lg   : 64*132            = 8448
// inv  : 128
// part : 256
#define SM_FW    0
#define SM_BIAS  (SM_FW + 64*128)
#define SM_XS    (SM_BIAS + 64)              // 8256 floats -> 33024 B, 16B aligned
#define SM_XT    (SM_XS + 128*XS_PAD)        // 25152 floats, 16B aligned
#define SM_LG    (SM_XT + 128*XT_PAD)        // 42304 floats
#define SM_INV   (SM_LG + 64*LG_PAD)         // 50752
#define SM_PART  (SM_INV + 128)              // 50880
#define SM_FLOATS (SM_PART + 256)            // 51136 floats
#define SMEM_BYTES (SM_FLOATS * 4)           // 204544 B < 227KB opt-in limit

// Per-block partial outputs (no atomics -> deterministic)
__device__ __align__(16) float g_vlad[Ndim][BLOCKS_PER_N][Kdim][Cdim]; // 8 MB
__device__ __align__(16) float g_asum[Ndim][BLOCKS_PER_N][Kdim];

// ---- packed f32x2 helpers (sm_100a) ----
__device__ __forceinline__ unsigned long long dup2(float x) {
    unsigned long long r;
    asm("mov.b64 %0, {%1, %1};" : "=l"(r) : "f"(x));
    return r;
}
__device__ __forceinline__ unsigned long long fma2(unsigned long long a,
                                                   unsigned long long b,
                                                   unsigned long long c) {
    unsigned long long d;
    asm("fma.rn.f32x2 %0, %1, %2, %3;" : "=l"(d) : "l"(a), "l"(b), "l"(c));
    return d;
}

__global__ void __launch_bounds__(THREADS, 1)
netvlad_main(const float* __restrict__ x,
             const float* __restrict__ fc_w,
             const float* __restrict__ fc_b)
{
    extern __shared__ float smem[];
    float* fw   = smem + SM_FW;
    float* bias = smem + SM_BIAS;
    float* xs   = smem + SM_XS;
    float* xt   = smem + SM_XT;
    float* lg   = smem + SM_LG;
    float* inv  = smem + SM_INV;
    float* part = smem + SM_PART;

    const int b   = blockIdx.x;
    const int n   = b / BLOCKS_PER_N;
    const int bi  = b % BLOCKS_PER_N;
    const int tid = threadIdx.x;
    const int kg  = tid >> 4;   // 0..15  (k group: k = 4*kg + j)
    const int sg  = tid & 15;   // 0..15  (s/c group: 2*sg + 32*i pairs)

    // load fc_w + bias into shared
    {
        const float4* src = (const float4*)fc_w;
        float4* dst = (float4*)fw;
        #pragma unroll
        for (int i = 0; i < (64*128/4)/THREADS; i++)
            dst[tid + i*THREADS] = src[tid + i*THREADS];
        if (tid < 64) bias[tid] = fc_b[tid];
    }

    // persistent vlad accumulators: k = 4*kg+j, c-pair = (2*sg+32*i, +1)
    unsigned long long vacc[4][4];
    #pragma unroll
    for (int j = 0; j < 4; j++)
        #pragma unroll
        for (int i = 0; i < 4; i++) vacc[j][i] = 0ULL;

    float asum_reg = 0.f;            // thread owns (k = tid&63, s-quarter = tid>>6)
    const int ak = tid & 63, aq = tid >> 6;

    __syncthreads();

    const float* xbase = x + (size_t)n * Cdim * Sdim;

    for (int tt = 0; tt < TILES_PER_BLOCK; tt++) {
        const int s0 = (bi * TILES_PER_BLOCK + tt) * TILE_S;

        // ---- 1. load raw x tile (coalesced float4, conflict-free STS.128) ----
        #pragma unroll
        for (int i = 0; i < 16; i++) {
            int idx = tid + i * THREADS;       // 0..4095 float4s
            int c   = idx >> 5;                // 0..127
            int s4  = idx & 31;                // 0..31
            float4 v = *(const float4*)(xbase + (size_t)c * Sdim + s0 + s4 * 4);
            *(float4*)(xs + c * XS_PAD + s4 * 4) = v;
        }
        __syncthreads();

        // ---- 2. per-s sum of squares over C ----
        {
            int s = tid & 127, half = tid >> 7;
            float ss = 0.f;
            int c0 = half * 64;
            #pragma unroll 8
            for (int c = c0; c < c0 + 64; c++) {
                float v = xs[c * XS_PAD + s];
                ss += v * v;
            }
            part[half * 128 + s] = ss;
        }
        __syncthreads();
        if (tid < 128) {
            float ss = part[tid] + part[128 + tid];
            inv[tid] = 1.0f / fmaxf(sqrtf(ss), 1e-12f);
        }
        __syncthreads();

        // ---- 3. scale in place + transposed copy ----
        {
            int s = tid & 127, crow = tid >> 7;
            float iv = inv[s];
            #pragma unroll 8
            for (int ci = 0; ci < 64; ci++) {
                int c = 2 * ci + crow;
                float v = xs[c * XS_PAD + s] * iv;
                xs[c * XS_PAD + s] = v;
                xt[s * XT_PAD + c] = v;
            }
        }
        __syncthreads();

        // ---- 4. GEMM1: logits[k][s] = fw[k]·xn[:,s] + b[k]  (f32x2 over s-pairs) ----
        {
            unsigned long long acc[4][4];
            #pragma unroll
            for (int j = 0; j < 4; j++) {
                unsigned long long bj = dup2(bias[4 * kg + j]);
                #pragma unroll
                for (int i = 0; i < 4; i++) acc[j][i] = bj;
            }
            #pragma unroll 4
            for (int c = 0; c < Cdim; c++) {
                unsigned long long bv[4];
                #pragma unroll
                for (int i = 0; i < 4; i++)
                    bv[i] = *(const unsigned long long*)(xs + c * XS_PAD + 2 * sg + 32 * i);
                #pragma unroll
                for (int j = 0; j < 4; j++) {
                    unsigned long long a = dup2(fw[(4 * kg + j) * Cdim + c]);
                    #pragma unroll
                    for (int i = 0; i < 4; i++)
                        acc[j][i] = fma2(a, bv[i], acc[j][i]);
                }
            }
            #pragma unroll
            for (int j = 0; j < 4; j++)
                #pragma unroll
                for (int i = 0; i < 4; i++)
                    *(unsigned long long*)(lg + (4 * kg + j) * LG_PAD + 2 * sg + 32 * i) = acc[j][i];
        }
        __syncthreads();

        // ---- 5. softmax over K per s-column (threads 0..127) ----
        if (tid < 128) {
            int s = tid;
            float vals[64];
            float m = -1e30f;
            #pragma unroll
            for (int k = 0; k < 64; k++) {
                float v = lg[k * LG_PAD + s];
                vals[k] = v;
                m = fmaxf(m, v);
            }
            float sum = 0.f;
            #pragma unroll
            for (int k = 0; k < 64; k++) {
                float e = __expf(vals[k] - m);
                vals[k] = e;
                sum += e;
            }
            float r = 1.0f / sum;
            #pragma unroll
            for (int k = 0; k < 64; k++)
                lg[k * LG_PAD + s] = vals[k] * r;
        }
        __syncthreads();

        // ---- 6a. a_sum partials ----
        {
            const float* row = lg + ak * LG_PAD + aq * 32;
            #pragma unroll 8
            for (int si = 0; si < 32; si++) asum_reg += row[si];
        }
        // ---- 6b. GEMM2: vlad[k][c] += sum_s soft[k][s] * xn[c][s]  (f32x2 over c-pairs) ----
        {
            #pragma unroll 2
            for (int s = 0; s < TILE_S; s++) {
                unsigned long long pv[4];
                #pragma unroll
                for (int j = 0; j < 4; j++)
                    pv[j] = dup2(lg[(4 * kg + j) * LG_PAD + s]);
                #pragma unroll
                for (int i = 0; i < 4; i++) {
                    unsigned long long xv =
                        *(const unsigned long long*)(xt + s * XT_PAD + 2 * sg + 32 * i);
                    #pragma unroll
                    for (int j = 0; j < 4; j++)
                        vacc[j][i] = fma2(pv[j], xv, vacc[j][i]);
                }
            }
        }
        __syncthreads();  // protect xs/xt/lg before next tile overwrites
    }

    // ---- flush per-block partials ----
    #pragma unroll
    for (int j = 0; j < 4; j++) {
        int k = 4 * kg + j;
        #pragma unroll
        for (int i = 0; i < 4; i++) {
            int c = 2 * sg + 32 * i;
            *(unsigned long long*)&g_vlad[n][bi][k][c] = vacc[j][i];
        }
    }
    part[tid] = asum_reg;  // tid == aq*64 + ak
    __syncthreads();
    if (tid < 64)
        g_asum[n][bi][tid] = part[tid] + part[64 + tid] + part[128 + tid] + part[192 + tid];
}

__global__ void __launch_bounds__(256, 1)
netvlad_epi(const float* __restrict__ centroids, float* __restrict__ out)
{
    __shared__ float w[Kdim * Cdim];   // 8192
    __shared__ float asum[Kdim];
    __shared__ float kinv[Kdim];
    __shared__ float rows[Kdim];
    __shared__ float ginv_sh;

    const int n = blockIdx.x;
    const int tid = threadIdx.x;

    if (tid < Kdim) {
        float a = 0.f;
        #pragma unroll
        for (int b = 0; b < BLOCKS_PER_N; b++) a += g_asum[n][b][tid];
        asum[tid] = a;
    }
    __syncthreads();

    // sum partials, subtract a_sum * centroid
    #pragma unroll
    for (int i = 0; i < 32; i++) {
        int e = tid + 256 * i;
        int k = e >> 7, c = e & 127;
        float v = 0.f;
        #pragma unroll
        for (int b = 0; b < BLOCKS_PER_N; b++) v += g_vlad[n][b][k][c];
        v -= asum[k] * centroids[k * Cdim + c];
        w[e] = v;
    }
    __syncthreads();

    // intra-normalization (per k row, deterministic serial-per-row sums)
    if (tid < Kdim) {
        float ss = 0.f;
        #pragma unroll 8
        for (int c = 0; c < Cdim; c++) {
            float v = w[tid * Cdim + c];
            ss += v * v;
        }
        kinv[tid] = 1.0f / fmaxf(sqrtf(ss), 1e-12f);
    }
    __syncthreads();
    #pragma unroll
    for (int i = 0; i < 32; i++) {
        int e = tid + 256 * i;
        w[e] = w[e] * kinv[e >> 7];
    }
    __syncthreads();

    // final global L2 norm
    if (tid < Kdim) {
        float ss = 0.f;
        #pragma unroll 8
        for (int c = 0; c < Cdim; c++) {
            float v = w[tid * Cdim + c];
            ss += v * v;
        }
        rows[tid] = ss;
    }
    __syncthreads();
    if (tid == 0) {
        float g = 0.f;
        #pragma unroll
        for (int k = 0; k < Kdim; k++) g += rows[k];
        ginv_sh = 1.0f / fmaxf(sqrtf(g), 1e-12f);
    }
    __syncthreads();

    float gi = ginv_sh;
    #pragma unroll
    for (int i = 0; i < 32; i++) {
        int e = tid + 256 * i;
        out[n * (Kdim * Cdim) + e] = w[e] * gi;
    }
}

extern "C" void kernel_launch(void* const* d_in, const int* in_sizes, int n_in,
                              void* d_out, int out_size)
{
    const float* x         = (const float*)d_in[0];
    const float* fc_w      = (const float*)d_in[1];
    const float* fc_b      = (const float*)d_in[2];
    const float* centroids = (const float*)d_in[3];
    float* out = (float*)d_out;

    cudaFuncSetAttribute(netvlad_main,
                         cudaFuncAttributeMaxDynamicSharedMemorySize, SMEM_BYTES);
    netvlad_main<<<GRID, THREADS, SMEM_BYTES>>>(x, fc_w, fc_b);
    netvlad_epi<<<Ndim, 256>>>(centroids, out);
}

// round 2
// speedup vs baseline: 1.0004x; 1.0004x over previous
#include <cuda_runtime.h>
#include <cstdint>

#define Ndim 16
#define Cdim 128
#define Sdim 16384
#define Kdim 64
#define TILE_S 128
#define THREADS 256
#define TILES_PER_BLOCK 8
#define BLOCKS_PER_N 16   // 16 blocks * 8 tiles * 128 s = 16384 = Sdim
#define GRID (Ndim * BLOCKS_PER_N)

#define XS_PAD 132   // xs[c][s], stride 132: GEMM1 b-loads contiguous, conflict-free
#define XT_PAD 134   // xt[s][c], stride 134: write bank stride 6 -> 2-way worst case
#define LG_PAD 132

// Shared layout (floats):
// fw   : 64*128            = 8192
// bias : 64
// xs   : 128*132           = 16896
// xt   : 128*134           = 17152
// lg   : 64*132            = 8448
// inv  : 128
// part : 256
#define SM_FW    0
#define SM_BIAS  (SM_FW + 64*128)
#define SM_XS    (SM_BIAS + 64)              // 8256 floats -> 33024 B, 16B aligned
#define SM_XT    (SM_XS + 128*XS_PAD)        // 25152 floats, 16B aligned
#define SM_LG    (SM_XT + 128*XT_PAD)        // 42304 floats
#define SM_INV   (SM_LG + 64*LG_PAD)         // 50752
#define SM_PART  (SM_INV + 128)              // 50880
#define SM_FLOATS (SM_PART + 256)            // 51136 floats
#define SMEM_BYTES (SM_FLOATS * 4)           // 204544 B < 227KB opt-in limit

// Per-block partial outputs (no atomics -> deterministic)
__device__ __align__(16) float g_vlad[Ndim][BLOCKS_PER_N][Kdim][Cdim]; // 8 MB
__device__ __align__(16) float g_asum[Ndim][BLOCKS_PER_N][Kdim];

// ---- packed f32x2 helpers (sm_100a) ----
__device__ __forceinline__ unsigned long long dup2(float x) {
    unsigned long long r;
    asm("mov.b64 %0, {%1, %1};" : "=l"(r) : "f"(x));
    return r;
}
__device__ __forceinline__ unsigned long long fma2(unsigned long long a,
                                                   unsigned long long b,
                                                   unsigned long long c) {
    unsigned long long d;
    asm("fma.rn.f32x2 %0, %1, %2, %3;" : "=l"(d) : "l"(a), "l"(b), "l"(c));
    return d;
}

__global__ void __launch_bounds__(THREADS, 1)
netvlad_main(const float* __restrict__ x,
             const float* __restrict__ fc_w,
             const float* __restrict__ fc_b)
{
    extern __shared__ float smem[];
    float* fw   = smem + SM_FW;
    float* bias = smem + SM_BIAS;
    float* xs   = smem + SM_XS;
    float* xt   = smem + SM_XT;
    float* lg   = smem + SM_LG;
    float* inv  = smem + SM_INV;
    float* part = smem + SM_PART;

    const int b   = blockIdx.x;
    const int n   = b / BLOCKS_PER_N;
    const int bi  = b % BLOCKS_PER_N;
    const int tid = threadIdx.x;
    const int kg  = tid >> 4;   // 0..15  (k group: k = 4*kg + j)
    const int sg  = tid & 15;   // 0..15  (s/c group: 2*sg + 32*i pairs)

    // load fc_w + bias into shared
    {
        const float4* src = (const float4*)fc_w;
        float4* dst = (float4*)fw;
        #pragma unroll
        for (int i = 0; i < (64*128/4)/THREADS; i++)
            dst[tid + i*THREADS] = src[tid + i*THREADS];
        if (tid < 64) bias[tid] = fc_b[tid];
    }

    // persistent vlad accumulators: k = 4*kg+j, c-pair = (2*sg+32*i, +1)
    unsigned long long vacc[4][4];
    #pragma unroll
    for (int j = 0; j < 4; j++)
        #pragma unroll
        for (int i = 0; i < 4; i++) vacc[j][i] = 0ULL;

    float asum_reg = 0.f;            // thread owns (k = tid&63, s-quarter = tid>>6)
    const int ak = tid & 63, aq = tid >> 6;

    __syncthreads();

    const float* xbase = x + (size_t)n * Cdim * Sdim;

    for (int tt = 0; tt < TILES_PER_BLOCK; tt++) {
        const int s0 = (bi * TILES_PER_BLOCK + tt) * TILE_S;

        // ---- 1. load raw x tile (coalesced float4, conflict-free STS.128) ----
        #pragma unroll
        for (int i = 0; i < 16; i++) {
            int idx = tid + i * THREADS;       // 0..4095 float4s
            int c   = idx >> 5;                // 0..127
            int s4  = idx & 31;                // 0..31
            float4 v = *(const float4*)(xbase + (size_t)c * Sdim + s0 + s4 * 4);
            *(float4*)(xs + c * XS_PAD + s4 * 4) = v;
        }
        __syncthreads();

        // ---- 2. per-s sum of squares over C ----
        {
            int s = tid & 127, half = tid >> 7;
            float ss = 0.f;
            int c0 = half * 64;
            #pragma unroll 8
            for (int c = c0; c < c0 + 64; c++) {
                float v = xs[c * XS_PAD + s];
                ss += v * v;
            }
            part[half * 128 + s] = ss;
        }
        __syncthreads();
        if (tid < 128) {
            float ss = part[tid] + part[128 + tid];
            inv[tid] = 1.0f / fmaxf(sqrtf(ss), 1e-12f);
        }
        __syncthreads();

        // ---- 3. scale in place + transposed copy ----
        {
            int s = tid & 127, crow = tid >> 7;
            float iv = inv[s];
            #pragma unroll 8
            for (int ci = 0; ci < 64; ci++) {
                int c = 2 * ci + crow;
                float v = xs[c * XS_PAD + s] * iv;
                xs[c * XS_PAD + s] = v;
                xt[s * XT_PAD + c] = v;
            }
        }
        __syncthreads();

        // ---- 4. GEMM1: logits[k][s] = fw[k]·xn[:,s] + b[k]  (f32x2 over s-pairs) ----
        {
            unsigned long long acc[4][4];
            #pragma unroll
            for (int j = 0; j < 4; j++) {
                unsigned long long bj = dup2(bias[4 * kg + j]);
                #pragma unroll
                for (int i = 0; i < 4; i++) acc[j][i] = bj;
            }
            #pragma unroll 4
            for (int c = 0; c < Cdim; c++) {
                unsigned long long bv[4];
                #pragma unroll
                for (int i = 0; i < 4; i++)
                    bv[i] = *(const unsigned long long*)(xs + c * XS_PAD + 2 * sg + 32 * i);
                #pragma unroll
                for (int j = 0; j < 4; j++) {
                    unsigned long long a = dup2(fw[(4 * kg + j) * Cdim + c]);
                    #pragma unroll
                    for (int i = 0; i < 4; i++)
                        acc[j][i] = fma2(a, bv[i], acc[j][i]);
                }
            }
            #pragma unroll
            for (int j = 0; j < 4; j++)
                #pragma unroll
                for (int i = 0; i < 4; i++)
                    *(unsigned long long*)(lg + (4 * kg + j) * LG_PAD + 2 * sg + 32 * i) = acc[j][i];
        }
        __syncthreads();

        // ---- 5. softmax over K per s-column (threads 0..127) ----
        if (tid < 128) {
            int s = tid;
            float vals[64];
            float m = -1e30f;
            #pragma unroll
            for (int k = 0; k < 64; k++) {
                float v = lg[k * LG_PAD + s];
                vals[k] = v;
                m = fmaxf(m, v);
            }
            float sum = 0.f;
            #pragma unroll
            for (int k = 0; k < 64; k++) {
                float e = __expf(vals[k] - m);
                vals[k] = e;
                sum += e;
            }
            float r = 1.0f / sum;
            #pragma unroll
            for (int k = 0; k < 64; k++)
                lg[k * LG_PAD + s] = vals[k] * r;
        }
        __syncthreads();

        // ---- 6a. a_sum partials ----
        {
            const float* row = lg + ak * LG_PAD + aq * 32;
            #pragma unroll 8
            for (int si = 0; si < 32; si++) asum_reg += row[si];
        }
        // ---- 6b. GEMM2: vlad[k][c] += sum_s soft[k][s] * xn[c][s]  (f32x2 over c-pairs) ----
        {
            #pragma unroll 2
            for (int s = 0; s < TILE_S; s++) {
                unsigned long long pv[4];
                #pragma unroll
                for (int j = 0; j < 4; j++)
                    pv[j] = dup2(lg[(4 * kg + j) * LG_PAD + s]);
                #pragma unroll
                for (int i = 0; i < 4; i++) {
                    unsigned long long xv =
                        *(const unsigned long long*)(xt + s * XT_PAD + 2 * sg + 32 * i);
                    #pragma unroll
                    for (int j = 0; j < 4; j++)
                        vacc[j][i] = fma2(pv[j], xv, vacc[j][i]);
                }
            }
        }
        __syncthreads();  // protect xs/xt/lg before next tile overwrites
    }

    // ---- flush per-block partials ----
    #pragma unroll
    for (int j = 0; j < 4; j++) {
        int k = 4 * kg + j;
        #pragma unroll
        for (int i = 0; i < 4; i++) {
            int c = 2 * sg + 32 * i;
            *(unsigned long long*)&g_vlad[n][bi][k][c] = vacc[j][i];
        }
    }
    part[tid] = asum_reg;  // tid == aq*64 + ak
    __syncthreads();
    if (tid < 64)
        g_asum[n][bi][tid] = part[tid] + part[64 + tid] + part[128 + tid] + part[192 + tid];
}

__global__ void __launch_bounds__(256, 1)
netvlad_epi(const float* __restrict__ centroids, float* __restrict__ out)
{
    __shared__ float w[Kdim * Cdim];   // 8192
    __shared__ float asum[Kdim];
    __shared__ float kinv[Kdim];
    __shared__ float rows[Kdim];
    __shared__ float ginv_sh;

    const int n = blockIdx.x;
    const int tid = threadIdx.x;

    if (tid < Kdim) {
        float a = 0.f;
        #pragma unroll
        for (int b = 0; b < BLOCKS_PER_N; b++) a += g_asum[n][b][tid];
        asum[tid] = a;
    }
    __syncthreads();

    // sum partials, subtract a_sum * centroid
    #pragma unroll
    for (int i = 0; i < 32; i++) {
        int e = tid + 256 * i;
        int k = e >> 7, c = e & 127;
        float v = 0.f;
        #pragma unroll
        for (int b = 0; b < BLOCKS_PER_N; b++) v += g_vlad[n][b][k][c];
        v -= asum[k] * centroids[k * Cdim + c];
        w[e] = v;
    }
    __syncthreads();

    // intra-normalization (per k row, deterministic serial-per-row sums)
    if (tid < Kdim) {
        float ss = 0.f;
        #pragma unroll 8
        for (int c = 0; c < Cdim; c++) {
            float v = w[tid * Cdim + c];
            ss += v * v;
        }
        kinv[tid] = 1.0f / fmaxf(sqrtf(ss), 1e-12f);
    }
    __syncthreads();
    #pragma unroll
    for (int i = 0; i < 32; i++) {
        int e = tid + 256 * i;
        w[e] = w[e] * kinv[e >> 7];
    }
    __syncthreads();

    // final global L2 norm
    if (tid < Kdim) {
        float ss = 0.f;
        #pragma unroll 8
        for (int c = 0; c < Cdim; c++) {
            float v = w[tid * Cdim + c];
            ss += v * v;
        }
        rows[tid] = ss;
    }
    __syncthreads();
    if (tid == 0) {
        float g = 0.f;
        #pragma unroll
        for (int k = 0; k < Kdim; k++) g += rows[k];
        ginv_sh = 1.0f / fmaxf(sqrtf(g), 1e-12f);
    }
    __syncthreads();

    float gi = ginv_sh;
    #pragma unroll
    for (int i = 0; i < 32; i++) {
        int e = tid + 256 * i;
        out[n * (Kdim * Cdim) + e] = w[e] * gi;
    }
}

extern "C" void kernel_launch(void* const* d_in, const int* in_sizes, int n_in,
                              void* d_out, int out_size)
{
    const float* x         = (const float*)d_in[0];
    const float* fc_w      = (const float*)d_in[1];
    const float* fc_b      = (const float*)d_in[2];
    const float* centroids = (const float*)d_in[3];
    float* out = (float*)d_out;

    cudaFuncSetAttribute(netvlad_main,
                         cudaFuncAttributeMaxDynamicSharedMemorySize, SMEM_BYTES);
    netvlad_main<<<GRID, THREADS, SMEM_BYTES>>>(x, fc_w, fc_b);
    netvlad_epi<<<Ndim, 256>>>(centroids, out);
}